// round 15
// baseline (speedup 1.0000x reference)
#include <cuda_runtime.h>
#include <cuda_fp16.h>

#define NN 100000
#define NE 1600000
#define NF 256
#define NH 128
#define NC 8

#define NB_DEG 592           // exactly 4 blocks/SM on 148 SMs; leaves room for k_xw co-residency

// Scratch (static __device__ — no runtime allocation allowed)
__device__ __align__(16) __half d_gh[NN * NC];   // fp16(g * dinv_src), 1.6 MB L2-resident
__device__ __align__(16) float d_acc[NN * NC];   // raw edge sums; zero at load, re-zeroed by k_post
__device__ int   d_deg[NN];                      // zero at load; re-zeroed by k_xw
__device__ float d_dinv[NN];
__device__ __align__(16) float d_Wc[NF * NC];    // W1 @ Wfc
__device__ __align__(16) float d_bc[NC];         // b1 @ Wfc + bfc

// Detect whether edge_index is int64 (every odd 32-bit word == 0) or int32.
__device__ __forceinline__ bool ei_is64(const int* __restrict__ ei32) {
    return (__ldg(ei32 + 1) == 0) && (__ldg(ei32 + 3) == 0);
}

// ------- k1: fold the two linear layers (tiny, serial prologue) -------
__global__ void k_fold(const float* __restrict__ W1, const float* __restrict__ b1,
                       const float* __restrict__ Wfc, const float* __restrict__ bfc) {
    int t = blockIdx.x * blockDim.x + threadIdx.x;
    if (t < NF * NC) {
        int k = t >> 3, c = t & 7;
        float s = 0.f;
        #pragma unroll 8
        for (int j = 0; j < NH; j++)
            s = fmaf(__ldg(W1 + k * NH + j), __ldg(Wfc + j * NC + c), s);
        d_Wc[t] = s;
    }
    if (t < NC) {
        float s = bfc[t];
        for (int j = 0; j < NH; j++) s = fmaf(b1[j], Wfc[j * NC + t], s);
        d_bc[t] = s;
    }
}

// ------- k2: degree histogram, occupancy-capped grid-stride; triggers PDL at entry -------
__global__ void __launch_bounds__(256) k_deg(const int* __restrict__ ei32) {
    cudaTriggerProgrammaticLaunchCompletion();     // let k_xw co-schedule immediately
    bool is64 = ei_is64(ei32);
    const int NQ = NE / 4;                          // 400000 quads
    for (int q = blockIdx.x * 256 + threadIdx.x; q < NQ; q += NB_DEG * 256) {
        int d0, d1, d2, d3;
        if (is64) {
            const int4* p = (const int4*)(ei32 + 2 * (size_t)NE);
            int4 a = p[q * 2], b = p[q * 2 + 1];
            d0 = a.x; d1 = a.z; d2 = b.x; d3 = b.z;
        } else {
            int4 a = ((const int4*)(ei32 + NE))[q];
            d0 = a.x; d1 = a.y; d2 = a.z; d3 = a.w;
        }
        atomicAdd(&d_deg[d0], 1);
        atomicAdd(&d_deg[d1], 1);
        atomicAdd(&d_deg[d2], 1);
        atomicAdd(&d_deg[d3], 1);
    }
}

// ------- k3 (PDL on k_deg): GEMM overlaps deg atomics; sync only before epilogue -------
#define KC 32                    // k-chunk
#define XS 33                    // smem row stride (floats)
__global__ void __launch_bounds__(256) k_xw(const float* __restrict__ x) {
    cudaTriggerProgrammaticLaunchCompletion();     // let k_edges prelaunch + preload idx
    __shared__ __align__(16) float swc[NF * NC];   // 8 KB weights
    __shared__ float sx[8 * 32 * XS];              // 33.8 KB

    int t = threadIdx.x;
    int lane = t & 31, warp = t >> 5;

    #pragma unroll
    for (int i = 0; i < 2; i++)
        ((float4*)swc)[t + i * 256] = ((const float4*)d_Wc)[t + i * 256];   // k_fold done pre-k_deg
    __syncthreads();

    int rowbase = blockIdx.x * 256 + warp * 32;
    float* swx = sx + warp * 32 * XS;

    int r_[8], c4_[8];
    const float4* xbase[8];
    #pragma unroll
    for (int i = 0; i < 8; i++) {
        int j = lane + 32 * i;
        r_[i] = j >> 3; c4_[i] = j & 7;
        int grow = rowbase + r_[i];
        if (grow >= NN) grow = NN - 1;
        xbase[i] = (const float4*)x + (size_t)grow * 64 + c4_[i];
    }

    float acc[NC];
    #pragma unroll
    for (int c = 0; c < NC; c++) acc[c] = 0.f;

    float4 pre[8];
    #pragma unroll
    for (int i = 0; i < 8; i++) pre[i] = __ldg(xbase[i]);

    #pragma unroll 1
    for (int ch = 0; ch < NF / KC; ch++) {
        int k0 = ch * KC;
        #pragma unroll
        for (int i = 0; i < 8; i++) {
            float* dst = swx + r_[i] * XS + c4_[i] * 4;
            dst[0] = pre[i].x; dst[1] = pre[i].y; dst[2] = pre[i].z; dst[3] = pre[i].w;
        }
        __syncwarp();
        if (ch < NF / KC - 1) {
            #pragma unroll
            for (int i = 0; i < 8; i++) pre[i] = __ldg(xbase[i] + (k0 + KC) / 4);
        }
        const float* xrow = swx + lane * XS;
        #pragma unroll
        for (int k = 0; k < KC; k++) {
            float xv = xrow[k];
            float4 wA = *(const float4*)(swc + (k0 + k) * NC);
            float4 wB = *(const float4*)(swc + (k0 + k) * NC + 4);
            acc[0] = fmaf(xv, wA.x, acc[0]); acc[1] = fmaf(xv, wA.y, acc[1]);
            acc[2] = fmaf(xv, wA.z, acc[2]); acc[3] = fmaf(xv, wA.w, acc[3]);
            acc[4] = fmaf(xv, wB.x, acc[4]); acc[5] = fmaf(xv, wB.y, acc[5]);
            acc[6] = fmaf(xv, wB.z, acc[6]); acc[7] = fmaf(xv, wB.w, acc[7]);
        }
        __syncwarp();
    }

    // Wait for k_deg's atomics to be complete & visible, then epilogue.
    cudaGridDependencySynchronize();

    int row = rowbase + lane;
    if (row >= NN) return;
    int deg = d_deg[row] + 1;               // +1 self-loop
    float dv = rsqrtf((float)deg);
    __half2 h0 = __floats2half2_rn(acc[0] * dv, acc[1] * dv);
    __half2 h1 = __floats2half2_rn(acc[2] * dv, acc[3] * dv);
    __half2 h2 = __floats2half2_rn(acc[4] * dv, acc[5] * dv);
    __half2 h3 = __floats2half2_rn(acc[6] * dv, acc[7] * dv);
    ((uint4*)d_gh)[row] = make_uint4(*(unsigned*)&h0, *(unsigned*)&h1,
                                     *(unsigned*)&h2, *(unsigned*)&h3);
    d_dinv[row] = dv;
    d_deg[row] = 0;                         // reset for next graph replay
}

// ------- k4 (PDL on k_xw): preload idx, sync, then gather + RED -------
__global__ void k_edges(const int* __restrict__ ei32) {
    cudaTriggerProgrammaticLaunchCompletion();
    int t = blockIdx.x * blockDim.x + threadIdx.x;     // handles edges 2t, 2t+1
    if (2 * t >= NE) { cudaGridDependencySynchronize(); return; }
    bool is64 = ei_is64(ei32);
    int s0, s1, d0, d1;
    if (is64) {
        int4 a = ((const int4*)ei32)[t];
        int4 b = ((const int4*)(ei32 + 2 * (size_t)NE))[t];
        s0 = a.x; s1 = a.z; d0 = b.x; d1 = b.z;
    } else {
        int2 a = ((const int2*)ei32)[t];
        int2 b = ((const int2*)(ei32 + NE))[t];
        s0 = a.x; s1 = a.y; d0 = b.x; d1 = b.y;
    }

    cudaGridDependencySynchronize();        // gh must be complete past this point

    const uint4* gp = (const uint4*)d_gh;
    uint4 ga = __ldg(gp + s0);
    uint4 gb = __ldg(gp + s1);

    float2 a0 = __half22float2(*(const __half2*)&ga.x);
    float2 a1 = __half22float2(*(const __half2*)&ga.y);
    float2 a2 = __half22float2(*(const __half2*)&ga.z);
    float2 a3 = __half22float2(*(const __half2*)&ga.w);
    float2 c0 = __half22float2(*(const __half2*)&gb.x);
    float2 c1 = __half22float2(*(const __half2*)&gb.y);
    float2 c2 = __half22float2(*(const __half2*)&gb.z);
    float2 c3 = __half22float2(*(const __half2*)&gb.w);

    float4* oa = ((float4*)d_acc) + d0 * 2;
    float4* ob = ((float4*)d_acc) + d1 * 2;
    asm volatile("red.global.add.v4.f32 [%0], {%1, %2, %3, %4};"
                 :: "l"(oa), "f"(a0.x), "f"(a0.y), "f"(a1.x), "f"(a1.y) : "memory");
    asm volatile("red.global.add.v4.f32 [%0], {%1, %2, %3, %4};"
                 :: "l"(oa + 1), "f"(a2.x), "f"(a2.y), "f"(a3.x), "f"(a3.y) : "memory");
    asm volatile("red.global.add.v4.f32 [%0], {%1, %2, %3, %4};"
                 :: "l"(ob), "f"(c0.x), "f"(c0.y), "f"(c1.x), "f"(c1.y) : "memory");
    asm volatile("red.global.add.v4.f32 [%0], {%1, %2, %3, %4};"
                 :: "l"(ob + 1), "f"(c2.x), "f"(c2.y), "f"(c3.x), "f"(c3.y) : "memory");
}

// ------- k5 (PDL on k_edges): out = bc + dinv * (acc + gh); acc reset -------
__global__ void k_post(float* __restrict__ out) {
    cudaGridDependencySynchronize();
    int t = blockIdx.x * blockDim.x + threadIdx.x;
    int row = t >> 1, half = t & 1;
    if (row >= NN) return;
    float dv = d_dinv[row];
    float4 s = ((const float4*)d_acc)[row * 2 + half];
    uint2 g = ((const uint2*)d_gh)[row * 2 + half];
    float2 g0 = __half22float2(*(const __half2*)&g.x);
    float2 g1 = __half22float2(*(const __half2*)&g.y);
    float4 b = ((const float4*)d_bc)[half];
    ((float4*)out)[row * 2 + half] = make_float4(
        fmaf(dv, s.x + g0.x, b.x), fmaf(dv, s.y + g0.y, b.y),
        fmaf(dv, s.z + g1.x, b.z), fmaf(dv, s.w + g1.y, b.w));
    ((float4*)d_acc)[row * 2 + half] = make_float4(0.f, 0.f, 0.f, 0.f);
}

extern "C" void kernel_launch(void* const* d_in, const int* in_sizes, int n_in,
                              void* d_out, int out_size) {
    const float* x    = (const float*)d_in[0];
    const int*   ei32 = (const int*)d_in[1];   // [2, NE], int32 or int64 (auto-detected)
    const float* W1   = (const float*)d_in[2];
    const float* b1   = (const float*)d_in[3];
    const float* Wfc  = (const float*)d_in[4];
    const float* bfc  = (const float*)d_in[5];
    float* out        = (float*)d_out;

    k_fold<<<8, 256>>>(W1, b1, Wfc, bfc);
    k_deg<<<NB_DEG, 256>>>(ei32);

    cudaLaunchAttribute attr[1];
    attr[0].id = cudaLaunchAttributeProgrammaticStreamSerialization;
    attr[0].val.programmaticStreamSerializationAllowed = 1;

    {   // k_xw: overlaps k_deg's atomics
        cudaLaunchConfig_t cfg = {};
        cfg.gridDim = dim3((NN + 255) / 256);
        cfg.blockDim = dim3(256);
        cfg.attrs = attr; cfg.numAttrs = 1; cfg.stream = 0;
        cudaLaunchKernelEx(&cfg, k_xw, x);
    }
    {   // k_edges: prelaunch to preload idx under k_xw's tail
        cudaLaunchConfig_t cfg = {};
        cfg.gridDim = dim3((NE / 2 + 255) / 256);
        cfg.blockDim = dim3(256);
        cfg.attrs = attr; cfg.numAttrs = 1; cfg.stream = 0;
        cudaLaunchKernelEx(&cfg, k_edges, ei32);
    }
    {   // k_post: gap hiding
        cudaLaunchConfig_t cfg = {};
        cfg.gridDim = dim3((2 * NN + 255) / 256);
        cfg.blockDim = dim3(256);
        cfg.attrs = attr; cfg.numAttrs = 1; cfg.stream = 0;
        cudaLaunchKernelEx(&cfg, k_post, out);
    }
}

// round 16
// speedup vs baseline: 1.1182x; 1.1182x over previous
#include <cuda_runtime.h>
#include <cuda_fp16.h>

#define NN 100000
#define NE 1600000
#define NF 256
#define NH 128
#define NC 8

#define NB_FOLD 8
#define NB_DEG 1563       // deg blocks: 1024 edges each (4 edges/thread)

// Scratch (static __device__ — no runtime allocation allowed)
__device__ __align__(16) __half d_gh[NN * NC];   // fp16(g * dinv_src), 1.6 MB L2-resident
__device__ __align__(16) __half d_acc[NN * NC];  // fp16 edge sums; zero at load, re-zeroed by k_post
__device__ int   d_deg[NN];                      // zero at load; re-zeroed by k_xw
__device__ float d_dinv[NN];
__device__ __align__(16) float d_Wc[NF * NC];    // W1 @ Wfc
__device__ __align__(16) float d_bc[NC];         // b1 @ Wfc + bfc

// Detect whether edge_index is int64 (every odd 32-bit word == 0) or int32.
__device__ __forceinline__ bool ei_is64(const int* __restrict__ ei32) {
    return (__ldg(ei32 + 1) == 0) && (__ldg(ei32 + 3) == 0);
}

// ------- k1: weight fold (blocks 0..7) || degree histogram 4 edges/thread (rest) -------
__global__ void __launch_bounds__(256) k_pre(const int* __restrict__ ei32,
                                             const float* __restrict__ W1,
                                             const float* __restrict__ b1,
                                             const float* __restrict__ Wfc,
                                             const float* __restrict__ bfc) {
    int t = threadIdx.x;
    if (blockIdx.x < NB_FOLD) {
        int idx = blockIdx.x * 256 + t;
        if (idx < NF * NC) {
            int k = idx >> 3, c = idx & 7;
            float s = 0.f;
            #pragma unroll 8
            for (int j = 0; j < NH; j++)
                s = fmaf(__ldg(W1 + k * NH + j), __ldg(Wfc + j * NC + c), s);
            d_Wc[idx] = s;
        }
        if (idx < NC) {
            float s = bfc[idx];
            for (int j = 0; j < NH; j++) s = fmaf(b1[j], Wfc[j * NC + idx], s);
            d_bc[idx] = s;
        }
    } else {
        int e4 = (blockIdx.x - NB_FOLD) * 256 + t;     // handles edges 4*e4..+3
        if (4 * e4 >= NE) return;
        bool is64 = ei_is64(ei32);
        int d0, d1, d2, d3;
        if (is64) {
            const int4* p = (const int4*)(ei32 + 2 * (size_t)NE);
            int4 a = p[e4 * 2], b = p[e4 * 2 + 1];
            d0 = a.x; d1 = a.z; d2 = b.x; d3 = b.z;
        } else {
            int4 a = ((const int4*)(ei32 + NE))[e4];
            d0 = a.x; d1 = a.y; d2 = a.z; d3 = a.w;
        }
        atomicAdd(&d_deg[d0], 1);
        atomicAdd(&d_deg[d1], 1);
        atomicAdd(&d_deg[d2], 1);
        atomicAdd(&d_deg[d3], 1);
    }
}

// ------- k2: gh = fp16((X @ Wc) * dinv); dinv; deg reset -------
// Thread = one row; 32-k chunks; register-prefetch double buffering.
#define KC 32                    // k-chunk
#define XS 33                    // smem row stride (floats)
__global__ void __launch_bounds__(256) k_xw(const float* __restrict__ x) {
    __shared__ __align__(16) float swc[NF * NC];       // 8 KB weights
    __shared__ float sx[8 * 32 * XS];                  // 33.8 KB

    int t = threadIdx.x;
    int lane = t & 31, warp = t >> 5;

    #pragma unroll
    for (int i = 0; i < 2; i++)
        ((float4*)swc)[t + i * 256] = ((const float4*)d_Wc)[t + i * 256];
    __syncthreads();

    int rowbase = blockIdx.x * 256 + warp * 32;        // this warp's 32 rows
    float* swx = sx + warp * 32 * XS;

    int r_[8], c4_[8];
    const float4* xbase[8];
    #pragma unroll
    for (int i = 0; i < 8; i++) {
        int j = lane + 32 * i;
        r_[i] = j >> 3; c4_[i] = j & 7;
        int grow = rowbase + r_[i];
        if (grow >= NN) grow = NN - 1;
        xbase[i] = (const float4*)x + (size_t)grow * 64 + c4_[i];
    }

    float acc[NC];
    #pragma unroll
    for (int c = 0; c < NC; c++) acc[c] = 0.f;

    float4 pre[8];
    #pragma unroll
    for (int i = 0; i < 8; i++) pre[i] = __ldg(xbase[i]);

    #pragma unroll 1
    for (int ch = 0; ch < NF / KC; ch++) {
        int k0 = ch * KC;
        #pragma unroll
        for (int i = 0; i < 8; i++) {
            float* dst = swx + r_[i] * XS + c4_[i] * 4;
            dst[0] = pre[i].x; dst[1] = pre[i].y; dst[2] = pre[i].z; dst[3] = pre[i].w;
        }
        __syncwarp();
        if (ch < NF / KC - 1) {
            #pragma unroll
            for (int i = 0; i < 8; i++) pre[i] = __ldg(xbase[i] + (k0 + KC) / 4);
        }
        const float* xrow = swx + lane * XS;
        #pragma unroll
        for (int k = 0; k < KC; k++) {
            float xv = xrow[k];
            float4 wA = *(const float4*)(swc + (k0 + k) * NC);
            float4 wB = *(const float4*)(swc + (k0 + k) * NC + 4);
            acc[0] = fmaf(xv, wA.x, acc[0]); acc[1] = fmaf(xv, wA.y, acc[1]);
            acc[2] = fmaf(xv, wA.z, acc[2]); acc[3] = fmaf(xv, wA.w, acc[3]);
            acc[4] = fmaf(xv, wB.x, acc[4]); acc[5] = fmaf(xv, wB.y, acc[5]);
            acc[6] = fmaf(xv, wB.z, acc[6]); acc[7] = fmaf(xv, wB.w, acc[7]);
        }
        __syncwarp();
    }

    int row = rowbase + lane;
    if (row >= NN) return;
    int deg = d_deg[row] + 1;               // +1 self-loop
    float dv = rsqrtf((float)deg);
    __half2 h0 = __floats2half2_rn(acc[0] * dv, acc[1] * dv);
    __half2 h1 = __floats2half2_rn(acc[2] * dv, acc[3] * dv);
    __half2 h2 = __floats2half2_rn(acc[4] * dv, acc[5] * dv);
    __half2 h3 = __floats2half2_rn(acc[6] * dv, acc[7] * dv);
    ((uint4*)d_gh)[row] = make_uint4(*(unsigned*)&h0, *(unsigned*)&h1,
                                     *(unsigned*)&h2, *(unsigned*)&h3);
    d_dinv[row] = dv;
    d_deg[row] = 0;                         // reset for next graph replay
}

// ------- k3: edges -> fp16 sums. 2 edges/thread; pure gather + v4.f16x2 RED -------
__global__ void k_edges(const int* __restrict__ ei32) {
    int t = blockIdx.x * blockDim.x + threadIdx.x;     // handles edges 2t, 2t+1
    if (2 * t >= NE) return;
    bool is64 = ei_is64(ei32);
    int s0, s1, d0, d1;
    if (is64) {
        int4 a = ((const int4*)ei32)[t];
        int4 b = ((const int4*)(ei32 + 2 * (size_t)NE))[t];
        s0 = a.x; s1 = a.z; d0 = b.x; d1 = b.z;
    } else {
        int2 a = ((const int2*)ei32)[t];
        int2 b = ((const int2*)(ei32 + NE))[t];
        s0 = a.x; s1 = a.y; d0 = b.x; d1 = b.y;
    }
    const uint4* gp = (const uint4*)d_gh;
    uint4 ga = __ldg(gp + s0);
    uint4 gb = __ldg(gp + s1);

    uint4* oa = ((uint4*)d_acc) + d0;
    uint4* ob = ((uint4*)d_acc) + d1;
    asm volatile("red.global.add.noftz.v4.f16x2 [%0], {%1, %2, %3, %4};"
                 :: "l"(oa), "r"(ga.x), "r"(ga.y), "r"(ga.z), "r"(ga.w) : "memory");
    asm volatile("red.global.add.noftz.v4.f16x2 [%0], {%1, %2, %3, %4};"
                 :: "l"(ob), "r"(gb.x), "r"(gb.y), "r"(gb.z), "r"(gb.w) : "memory");
}

// ------- k4: out = bc + dinv * (acc + gh); acc reset. 1 thread/row -------
__global__ void k_post(float* __restrict__ out) {
    int row = blockIdx.x * blockDim.x + threadIdx.x;
    if (row >= NN) return;
    float dv = d_dinv[row];
    uint4 s = ((const uint4*)d_acc)[row];
    uint4 g = ((const uint4*)d_gh)[row];
    float2 s0 = __half22float2(*(const __half2*)&s.x);
    float2 s1 = __half22float2(*(const __half2*)&s.y);
    float2 s2 = __half22float2(*(const __half2*)&s.z);
    float2 s3 = __half22float2(*(const __half2*)&s.w);
    float2 g0 = __half22float2(*(const __half2*)&g.x);
    float2 g1 = __half22float2(*(const __half2*)&g.y);
    float2 g2 = __half22float2(*(const __half2*)&g.z);
    float2 g3 = __half22float2(*(const __half2*)&g.w);
    float4 b0 = ((const float4*)d_bc)[0];
    float4 b1 = ((const float4*)d_bc)[1];
    ((float4*)out)[row * 2] = make_float4(
        fmaf(dv, s0.x + g0.x, b0.x), fmaf(dv, s0.y + g0.y, b0.y),
        fmaf(dv, s1.x + g1.x, b0.z), fmaf(dv, s1.y + g1.y, b0.w));
    ((float4*)out)[row * 2 + 1] = make_float4(
        fmaf(dv, s2.x + g2.x, b1.x), fmaf(dv, s2.y + g2.y, b1.y),
        fmaf(dv, s3.x + g3.x, b1.z), fmaf(dv, s3.y + g3.y, b1.w));
    ((uint4*)d_acc)[row] = make_uint4(0u, 0u, 0u, 0u);   // reset for next replay
}

extern "C" void kernel_launch(void* const* d_in, const int* in_sizes, int n_in,
                              void* d_out, int out_size) {
    const float* x    = (const float*)d_in[0];
    const int*   ei32 = (const int*)d_in[1];   // [2, NE], int32 or int64 (auto-detected)
    const float* W1   = (const float*)d_in[2];
    const float* b1   = (const float*)d_in[3];
    const float* Wfc  = (const float*)d_in[4];
    const float* bfc  = (const float*)d_in[5];
    float* out        = (float*)d_out;

    k_pre<<<NB_FOLD + NB_DEG, 256>>>(ei32, W1, b1, Wfc, bfc);
    k_xw<<<(NN + 255) / 256, 256>>>(x);
    k_edges<<<(NE / 2 + 255) / 256, 256>>>(ei32);
    k_post<<<(NN + 255) / 256, 256>>>(out);
}

// round 17
// speedup vs baseline: 1.1474x; 1.0261x over previous
#include <cuda_runtime.h>
#include <cuda_fp16.h>

#define NN 100000
#define NE 1600000
#define NF 256
#define NH 128
#define NC 8

#define NB_FOLD 8
#define NB_DEG 1563       // deg blocks: 1024 edges each (4 edges/thread)

// Scratch (static __device__ — no runtime allocation allowed)
__device__ __align__(16) __half d_gh[NN * NC];   // fp16(g * dinv_src), 1.6 MB L2-resident
__device__ __align__(16) __half d_acc[NN * NC];  // fp16 edge sums; zero at load, re-zeroed by k_post
__device__ int   d_deg[NN];                      // zero at load; re-zeroed by k_xw
__device__ float d_dinv[NN];
__device__ __align__(16) float d_Wc[NF * NC];    // W1 @ Wfc
__device__ __align__(16) float d_bc[NC];         // b1 @ Wfc + bfc

// Detect whether edge_index is int64 (every odd 32-bit word == 0) or int32.
__device__ __forceinline__ bool ei_is64(const int* __restrict__ ei32) {
    return (__ldg(ei32 + 1) == 0) && (__ldg(ei32 + 3) == 0);
}

// ------- k1: weight fold (blocks 0..7) || degree histogram 4 edges/thread (rest) -------
__global__ void __launch_bounds__(256) k_pre(const int* __restrict__ ei32,
                                             const float* __restrict__ W1,
                                             const float* __restrict__ b1,
                                             const float* __restrict__ Wfc,
                                             const float* __restrict__ bfc) {
    int t = threadIdx.x;
    if (blockIdx.x < NB_FOLD) {
        int idx = blockIdx.x * 256 + t;
        if (idx < NF * NC) {
            int k = idx >> 3, c = idx & 7;
            float s = 0.f;
            #pragma unroll 8
            for (int j = 0; j < NH; j++)
                s = fmaf(__ldg(W1 + k * NH + j), __ldg(Wfc + j * NC + c), s);
            d_Wc[idx] = s;
        }
        if (idx < NC) {
            float s = bfc[idx];
            for (int j = 0; j < NH; j++) s = fmaf(b1[j], Wfc[j * NC + idx], s);
            d_bc[idx] = s;
        }
    } else {
        int e4 = (blockIdx.x - NB_FOLD) * 256 + t;     // handles edges 4*e4..+3
        if (4 * e4 >= NE) return;
        bool is64 = ei_is64(ei32);
        int d0, d1, d2, d3;
        if (is64) {
            const int4* p = (const int4*)(ei32 + 2 * (size_t)NE);
            int4 a = p[e4 * 2], b = p[e4 * 2 + 1];
            d0 = a.x; d1 = a.z; d2 = b.x; d3 = b.z;
        } else {
            int4 a = ((const int4*)(ei32 + NE))[e4];
            d0 = a.x; d1 = a.y; d2 = a.z; d3 = a.w;
        }
        atomicAdd(&d_deg[d0], 1);
        atomicAdd(&d_deg[d1], 1);
        atomicAdd(&d_deg[d2], 1);
        atomicAdd(&d_deg[d3], 1);
    }
}

// ------- k2: gh = fp16((X @ Wc) * dinv); dinv; deg reset -------
// 128-thread blocks (4 warps), 128 rows/block -> 782 blocks for SM balance.
// Thread = one row; 32-k chunks; register-prefetch double buffering.
#define KC 32                    // k-chunk
#define XS 33                    // smem row stride (floats)
#define XWT 128                  // threads per xw block
__global__ void __launch_bounds__(XWT) k_xw(const float* __restrict__ x) {
    __shared__ __align__(16) float swc[NF * NC];       // 8 KB weights
    __shared__ float sx[4 * 32 * XS];                  // 4 warps * 32 rows * 33 = 16.9 KB

    int t = threadIdx.x;
    int lane = t & 31, warp = t >> 5;

    #pragma unroll
    for (int i = 0; i < 4; i++)
        ((float4*)swc)[t + i * XWT] = ((const float4*)d_Wc)[t + i * XWT];
    __syncthreads();

    int rowbase = blockIdx.x * XWT + warp * 32;        // this warp's 32 rows
    float* swx = sx + warp * 32 * XS;

    int r_[8], c4_[8];
    const float4* xbase[8];
    #pragma unroll
    for (int i = 0; i < 8; i++) {
        int j = lane + 32 * i;
        r_[i] = j >> 3; c4_[i] = j & 7;
        int grow = rowbase + r_[i];
        if (grow >= NN) grow = NN - 1;
        xbase[i] = (const float4*)x + (size_t)grow * 64 + c4_[i];
    }

    float acc[NC];
    #pragma unroll
    for (int c = 0; c < NC; c++) acc[c] = 0.f;

    float4 pre[8];
    #pragma unroll
    for (int i = 0; i < 8; i++) pre[i] = __ldg(xbase[i]);

    #pragma unroll 1
    for (int ch = 0; ch < NF / KC; ch++) {
        int k0 = ch * KC;
        #pragma unroll
        for (int i = 0; i < 8; i++) {
            float* dst = swx + r_[i] * XS + c4_[i] * 4;
            dst[0] = pre[i].x; dst[1] = pre[i].y; dst[2] = pre[i].z; dst[3] = pre[i].w;
        }
        __syncwarp();
        if (ch < NF / KC - 1) {
            #pragma unroll
            for (int i = 0; i < 8; i++) pre[i] = __ldg(xbase[i] + (k0 + KC) / 4);
        }
        const float* xrow = swx + lane * XS;
        #pragma unroll
        for (int k = 0; k < KC; k++) {
            float xv = xrow[k];
            float4 wA = *(const float4*)(swc + (k0 + k) * NC);
            float4 wB = *(const float4*)(swc + (k0 + k) * NC + 4);
            acc[0] = fmaf(xv, wA.x, acc[0]); acc[1] = fmaf(xv, wA.y, acc[1]);
            acc[2] = fmaf(xv, wA.z, acc[2]); acc[3] = fmaf(xv, wA.w, acc[3]);
            acc[4] = fmaf(xv, wB.x, acc[4]); acc[5] = fmaf(xv, wB.y, acc[5]);
            acc[6] = fmaf(xv, wB.z, acc[6]); acc[7] = fmaf(xv, wB.w, acc[7]);
        }
        __syncwarp();
    }

    int row = rowbase + lane;
    if (row >= NN) return;
    int deg = d_deg[row] + 1;               // +1 self-loop
    float dv = rsqrtf((float)deg);
    __half2 h0 = __floats2half2_rn(acc[0] * dv, acc[1] * dv);
    __half2 h1 = __floats2half2_rn(acc[2] * dv, acc[3] * dv);
    __half2 h2 = __floats2half2_rn(acc[4] * dv, acc[5] * dv);
    __half2 h3 = __floats2half2_rn(acc[6] * dv, acc[7] * dv);
    ((uint4*)d_gh)[row] = make_uint4(*(unsigned*)&h0, *(unsigned*)&h1,
                                     *(unsigned*)&h2, *(unsigned*)&h3);
    d_dinv[row] = dv;
    d_deg[row] = 0;                         // reset for next graph replay
}

// ------- k3: edges -> fp16 sums. 2 edges/thread; pure gather + v4.f16x2 RED -------
__global__ void k_edges(const int* __restrict__ ei32) {
    int t = blockIdx.x * blockDim.x + threadIdx.x;     // handles edges 2t, 2t+1
    if (2 * t >= NE) return;
    bool is64 = ei_is64(ei32);
    int s0, s1, d0, d1;
    if (is64) {
        int4 a = ((const int4*)ei32)[t];
        int4 b = ((const int4*)(ei32 + 2 * (size_t)NE))[t];
        s0 = a.x; s1 = a.z; d0 = b.x; d1 = b.z;
    } else {
        int2 a = ((const int2*)ei32)[t];
        int2 b = ((const int2*)(ei32 + NE))[t];
        s0 = a.x; s1 = a.y; d0 = b.x; d1 = b.y;
    }
    const uint4* gp = (const uint4*)d_gh;
    uint4 ga = __ldg(gp + s0);
    uint4 gb = __ldg(gp + s1);

    uint4* oa = ((uint4*)d_acc) + d0;
    uint4* ob = ((uint4*)d_acc) + d1;
    asm volatile("red.global.add.noftz.v4.f16x2 [%0], {%1, %2, %3, %4};"
                 :: "l"(oa), "r"(ga.x), "r"(ga.y), "r"(ga.z), "r"(ga.w) : "memory");
    asm volatile("red.global.add.noftz.v4.f16x2 [%0], {%1, %2, %3, %4};"
                 :: "l"(ob), "r"(gb.x), "r"(gb.y), "r"(gb.z), "r"(gb.w) : "memory");
}

// ------- k4: out = bc + dinv * (acc + gh); acc reset. 1 thread/row -------
__global__ void k_post(float* __restrict__ out) {
    int row = blockIdx.x * blockDim.x + threadIdx.x;
    if (row >= NN) return;
    float dv = d_dinv[row];
    uint4 s = ((const uint4*)d_acc)[row];
    uint4 g = ((const uint4*)d_gh)[row];
    float2 s0 = __half22float2(*(const __half2*)&s.x);
    float2 s1 = __half22float2(*(const __half2*)&s.y);
    float2 s2 = __half22float2(*(const __half2*)&s.z);
    float2 s3 = __half22float2(*(const __half2*)&s.w);
    float2 g0 = __half22float2(*(const __half2*)&g.x);
    float2 g1 = __half22float2(*(const __half2*)&g.y);
    float2 g2 = __half22float2(*(const __half2*)&g.z);
    float2 g3 = __half22float2(*(const __half2*)&g.w);
    float4 b0 = ((const float4*)d_bc)[0];
    float4 b1 = ((const float4*)d_bc)[1];
    ((float4*)out)[row * 2] = make_float4(
        fmaf(dv, s0.x + g0.x, b0.x), fmaf(dv, s0.y + g0.y, b0.y),
        fmaf(dv, s1.x + g1.x, b0.z), fmaf(dv, s1.y + g1.y, b0.w));
    ((float4*)out)[row * 2 + 1] = make_float4(
        fmaf(dv, s2.x + g2.x, b1.x), fmaf(dv, s2.y + g2.y, b1.y),
        fmaf(dv, s3.x + g3.x, b1.z), fmaf(dv, s3.y + g3.y, b1.w));
    ((uint4*)d_acc)[row] = make_uint4(0u, 0u, 0u, 0u);   // reset for next replay
}

extern "C" void kernel_launch(void* const* d_in, const int* in_sizes, int n_in,
                              void* d_out, int out_size) {
    const float* x    = (const float*)d_in[0];
    const int*   ei32 = (const int*)d_in[1];   // [2, NE], int32 or int64 (auto-detected)
    const float* W1   = (const float*)d_in[2];
    const float* b1   = (const float*)d_in[3];
    const float* Wfc  = (const float*)d_in[4];
    const float* bfc  = (const float*)d_in[5];
    float* out        = (float*)d_out;

    k_pre<<<NB_FOLD + NB_DEG, 256>>>(ei32, W1, b1, Wfc, bfc);
    k_xw<<<(NN + XWT - 1) / XWT, XWT>>>(x);
    k_edges<<<(NE / 2 + 255) / 256, 256>>>(ei32);
    k_post<<<(NN + 255) / 256, 256>>>(out);
}